// round 2
// baseline (speedup 1.0000x reference)
#include <cuda_runtime.h>
#include <cuda_bf16.h>
#include <math.h>

// Problem constants
#define B_    2
#define T_    1024
#define EMB_  3584
#define NH_   28
#define KVH_  4
#define HD_   128
#define NREP_ 7
#define M_    (B_*T_)        // 2048 rows
#define QN_   (NH_*HD_)      // 3584
#define KN_   (KVH_*HD_)     // 512

// Scratch (device globals — no allocation allowed)
__device__ float g_q[(size_t)M_*QN_];
__device__ float g_k[(size_t)M_*KN_];
__device__ float g_v[(size_t)M_*KN_];
__device__ float g_att[(size_t)M_*QN_];
__device__ int   g_pos[B_*T_];
__device__ int   g_start[B_];

// ---------------------------------------------------------------------------
// Segment scan: positions = cumsum(valid)-1+cur_ind ; start = # leading pads
// ---------------------------------------------------------------------------
__global__ void scan_kernel(const int* __restrict__ seg, const int* __restrict__ curp) {
    __shared__ int s[T_];
    __shared__ int cnt;
    int b = blockIdx.x, t = threadIdx.x;
    if (t == 0) cnt = 0;
    int v = (seg[b*T_ + t] != 0) ? 1 : 0;
    s[t] = v;
    __syncthreads();
    for (int off = 1; off < T_; off <<= 1) {
        int x = (t >= off) ? s[t-off] : 0;
        __syncthreads();
        s[t] += x;
        __syncthreads();
    }
    int cum = s[t];
    g_pos[b*T_ + t] = cum - 1 + curp[0];
    if (cum == 0) atomicAdd(&cnt, 1);
    __syncthreads();
    if (t == 0) g_start[b] = cnt;
}

// ---------------------------------------------------------------------------
// RoPE (in place on [b,t,H,HD] tensor). Accurate-enough float path with
// Cody-Waite reduction so it stays correct under --use_fast_math.
// ---------------------------------------------------------------------------
__global__ void rope_kernel(float* __restrict__ x, int H, int total) {
    int idx = blockIdx.x * blockDim.x + threadIdx.x;
    if (idx >= total) return;
    int i  = idx & 63;
    int h  = (idx >> 6) % H;
    int bt = idx / (64 * H);
    int pos = g_pos[bt];
    // timescale = THETA^(2i/HD) = 2^(i * log2(1e6)/64)
    float ts  = exp2f((float)i * 0.311430758895742f);
    float ang = (float)pos / ts;
    // reduce ang mod 2*pi to [-pi, pi]
    float kq = rintf(ang * 0.15915494309189535f);
    float r  = fmaf(-kq, 6.28125f, ang);
    r        = fmaf(-kq, 1.9353071795864769e-3f, r);
    float sv, cv;
    sincosf(r, &sv, &cv);
    float* p = x + ((size_t)bt * H + h) * HD_;
    float x1 = p[i], x2 = p[i + 64];
    p[i]      = x1 * cv - x2 * sv;
    p[i + 64] = x2 * cv + x1 * sv;
}

// ---------------------------------------------------------------------------
// SGEMM: C[M_, N] = A[M_, EMB_] * Bw[EMB_, N] (+bias). 128x128x16 tiles,
// 256 threads, 8x8 per thread, fp32.
// ---------------------------------------------------------------------------
__global__ void __launch_bounds__(256)
sgemm_kernel(const float* __restrict__ A, const float* __restrict__ Bw,
             const float* __restrict__ bias, float* __restrict__ C, int N) {
    __shared__ float As[16][128];
    __shared__ float Bs[16][128];
    const int tid = threadIdx.x;
    const int tx = tid & 15, ty = tid >> 4;
    const int m0 = blockIdx.y * 128, n0 = blockIdx.x * 128;

    float acc[8][8];
    #pragma unroll
    for (int i = 0; i < 8; i++)
        #pragma unroll
        for (int j = 0; j < 8; j++) acc[i][j] = 0.f;

    for (int k0 = 0; k0 < EMB_; k0 += 16) {
        #pragma unroll
        for (int i = 0; i < 2; i++) {
            int lin = tid + 256 * i;         // 0..511 float4s
            int row = lin >> 2, kc = lin & 3;
            float4 v = *(const float4*)&A[(size_t)(m0 + row) * EMB_ + k0 + kc * 4];
            As[kc*4+0][row] = v.x; As[kc*4+1][row] = v.y;
            As[kc*4+2][row] = v.z; As[kc*4+3][row] = v.w;
        }
        #pragma unroll
        for (int i = 0; i < 2; i++) {
            int lin = tid + 256 * i;
            int kr = lin >> 5, nc = lin & 31;
            *(float4*)&Bs[kr][nc*4] =
                *(const float4*)&Bw[(size_t)(k0 + kr) * N + n0 + nc * 4];
        }
        __syncthreads();
        #pragma unroll
        for (int kk = 0; kk < 16; kk++) {
            float a[8], bb[8];
            *(float4*)&a[0]  = *(float4*)&As[kk][ty*4];
            *(float4*)&a[4]  = *(float4*)&As[kk][64 + ty*4];
            *(float4*)&bb[0] = *(float4*)&Bs[kk][tx*4];
            *(float4*)&bb[4] = *(float4*)&Bs[kk][64 + tx*4];
            #pragma unroll
            for (int i = 0; i < 8; i++)
                #pragma unroll
                for (int j = 0; j < 8; j++)
                    acc[i][j] = fmaf(a[i], bb[j], acc[i][j]);
        }
        __syncthreads();
    }

    #pragma unroll
    for (int i = 0; i < 8; i++) {
        int r = (i < 4) ? (ty*4 + i) : (64 + ty*4 + (i - 4));
        #pragma unroll
        for (int jb = 0; jb < 2; jb++) {
            int c = jb ? (64 + tx*4) : (tx*4);
            float4 v;
            v.x = acc[i][jb*4+0]; v.y = acc[i][jb*4+1];
            v.z = acc[i][jb*4+2]; v.w = acc[i][jb*4+3];
            if (bias) {
                v.x += bias[n0 + c + 0]; v.y += bias[n0 + c + 1];
                v.z += bias[n0 + c + 2]; v.w += bias[n0 + c + 3];
            }
            *(float4*)&C[(size_t)(m0 + r) * N + n0 + c] = v;
        }
    }
}

// ---------------------------------------------------------------------------
// Flash attention: 64 q-rows x 64 k-cols tiles, online softmax, fp32.
// grid (T/64, NH, B), 256 threads. K and V share one smem buffer.
// ---------------------------------------------------------------------------
#define QS_STRIDE 132
#define PS_STRIDE 68

__global__ void __launch_bounds__(256)
attn_kernel(const int* __restrict__ curp, float* __restrict__ out) {
    extern __shared__ float sm[];
    float* Qs  = sm;                       // 64 x 132
    float* KVs = sm + 64 * QS_STRIDE;      // 64 x 132
    float* Ps  = sm + 2 * 64 * QS_STRIDE;  // 64 x 68

    const int qt = blockIdx.x, h = blockIdx.y, b = blockIdx.z;
    const int kvh = h / NREP_;
    const int tid = threadIdx.x;
    const int tx = tid & 15, ty = tid >> 4;
    const int cur = curp[0];
    const int start = g_start[b];
    const float scale = 0.08838834764831845f;

    // load Q tile
    #pragma unroll
    for (int i = 0; i < 8; i++) {
        int lin = tid + 256 * i;           // 0..2047 float4s
        int row = lin >> 5, dc = lin & 31;
        float4 v = *(const float4*)&g_q[(((size_t)(b*T_ + qt*64 + row)) * NH_ + h) * HD_ + dc*4];
        *(float4*)&Qs[row * QS_STRIDE + dc*4] = v;
    }

    float o[4][8];
    float m[4], l[4];
    #pragma unroll
    for (int i = 0; i < 4; i++) {
        m[i] = -INFINITY; l[i] = 0.f;
        #pragma unroll
        for (int j = 0; j < 8; j++) o[i][j] = 0.f;
    }

    for (int kt = 0; kt <= qt; kt++) {
        __syncthreads();
        // load K tile
        #pragma unroll
        for (int i = 0; i < 8; i++) {
            int lin = tid + 256 * i;
            int row = lin >> 5, dc = lin & 31;
            float4 v = *(const float4*)&g_k[(((size_t)(b*T_ + kt*64 + row)) * KVH_ + kvh) * HD_ + dc*4];
            *(float4*)&KVs[row * QS_STRIDE + dc*4] = v;
        }
        __syncthreads();

        // S = Q K^T  (rows ty+16i, cols tx+16j)
        float sv[4][4];
        #pragma unroll
        for (int i = 0; i < 4; i++)
            #pragma unroll
            for (int j = 0; j < 4; j++) sv[i][j] = 0.f;
        #pragma unroll 8
        for (int d4 = 0; d4 < 32; d4++) {
            float4 qv[4], kv[4];
            #pragma unroll
            for (int i = 0; i < 4; i++)
                qv[i] = *(float4*)&Qs[(ty + 16*i) * QS_STRIDE + d4*4];
            #pragma unroll
            for (int j = 0; j < 4; j++)
                kv[j] = *(float4*)&KVs[(tx + 16*j) * QS_STRIDE + d4*4];
            #pragma unroll
            for (int i = 0; i < 4; i++)
                #pragma unroll
                for (int j = 0; j < 4; j++) {
                    sv[i][j] = fmaf(qv[i].x, kv[j].x, sv[i][j]);
                    sv[i][j] = fmaf(qv[i].y, kv[j].y, sv[i][j]);
                    sv[i][j] = fmaf(qv[i].z, kv[j].z, sv[i][j]);
                    sv[i][j] = fmaf(qv[i].w, kv[j].w, sv[i][j]);
                }
        }

        // mask + online softmax update
        #pragma unroll
        for (int i = 0; i < 4; i++) {
            int trow = qt*64 + ty + 16*i;
            int qpos = cur + trow - start;
            float mx = -INFINITY;
            #pragma unroll
            for (int j = 0; j < 4; j++) {
                int s = kt*64 + tx + 16*j;
                bool valid = (s >= start) && (s < cur + T_) && ((s - start) <= qpos);
                float val = valid ? sv[i][j] * scale : -INFINITY;
                sv[i][j] = val;
                mx = fmaxf(mx, val);
            }
            #pragma unroll
            for (int w = 8; w >= 1; w >>= 1)
                mx = fmaxf(mx, __shfl_xor_sync(0xffffffffu, mx, w));
            float mnew = fmaxf(m[i], mx);
            float alpha = expf(m[i] - mnew);
            float rs = 0.f;
            #pragma unroll
            for (int j = 0; j < 4; j++) {
                sv[i][j] = expf(sv[i][j] - mnew);
                rs += sv[i][j];
            }
            #pragma unroll
            for (int w = 8; w >= 1; w >>= 1)
                rs += __shfl_xor_sync(0xffffffffu, rs, w);
            l[i] = l[i] * alpha + rs;
            m[i] = mnew;
            #pragma unroll
            for (int j = 0; j < 8; j++) o[i][j] *= alpha;
            // write P
            #pragma unroll
            for (int j = 0; j < 4; j++)
                Ps[(ty + 16*i) * PS_STRIDE + tx + 16*j] = sv[i][j];
        }
        __syncthreads();   // all K reads + P writes done

        // load V tile into the same buffer
        #pragma unroll
        for (int i = 0; i < 8; i++) {
            int lin = tid + 256 * i;
            int row = lin >> 5, dc = lin & 31;
            float4 v = *(const float4*)&g_v[(((size_t)(b*T_ + kt*64 + row)) * KVH_ + kvh) * HD_ + dc*4];
            *(float4*)&KVs[row * QS_STRIDE + dc*4] = v;
        }
        __syncthreads();

        // O += P V   (cols tx*4+{0..3}, 64+tx*4+{0..3})
        #pragma unroll 8
        for (int k = 0; k < 64; k++) {
            float pk[4];
            #pragma unroll
            for (int i = 0; i < 4; i++) pk[i] = Ps[(ty + 16*i) * PS_STRIDE + k];
            float4 v0 = *(float4*)&KVs[k * QS_STRIDE + tx*4];
            float4 v1 = *(float4*)&KVs[k * QS_STRIDE + 64 + tx*4];
            #pragma unroll
            for (int i = 0; i < 4; i++) {
                o[i][0] = fmaf(pk[i], v0.x, o[i][0]);
                o[i][1] = fmaf(pk[i], v0.y, o[i][1]);
                o[i][2] = fmaf(pk[i], v0.z, o[i][2]);
                o[i][3] = fmaf(pk[i], v0.w, o[i][3]);
                o[i][4] = fmaf(pk[i], v1.x, o[i][4]);
                o[i][5] = fmaf(pk[i], v1.y, o[i][5]);
                o[i][6] = fmaf(pk[i], v1.z, o[i][6]);
                o[i][7] = fmaf(pk[i], v1.w, o[i][7]);
            }
        }
    }

    // normalize + store
    #pragma unroll
    for (int i = 0; i < 4; i++) {
        float inv = 1.0f / l[i];
        int trow = qt*64 + ty + 16*i;
        size_t base = (((size_t)(b*T_ + trow)) * NH_ + h) * HD_;
        float4 r0, r1;
        r0.x = o[i][0]*inv; r0.y = o[i][1]*inv; r0.z = o[i][2]*inv; r0.w = o[i][3]*inv;
        r1.x = o[i][4]*inv; r1.y = o[i][5]*inv; r1.z = o[i][6]*inv; r1.w = o[i][7]*inv;
        *(float4*)&out[base + tx*4]      = r0;
        *(float4*)&out[base + 64 + tx*4] = r1;
    }
}

// ---------------------------------------------------------------------------
// Launch
// ---------------------------------------------------------------------------
extern "C" void kernel_launch(void* const* d_in, const int* in_sizes, int n_in,
                              void* d_out, int out_size) {
    const float* x    = (const float*)d_in[0];
    const int*   seg  = (const int*)  d_in[1];
    // d_in[2], d_in[3]: k_cache/v_cache — unused (cur_ind=0, all keys fresh)
    const int*   curp = (const int*)  d_in[4];
    const float* wq   = (const float*)d_in[5];
    const float* bq   = (const float*)d_in[6];
    const float* wk   = (const float*)d_in[7];
    const float* bk   = (const float*)d_in[8];
    const float* wv   = (const float*)d_in[9];
    const float* bv   = (const float*)d_in[10];
    const float* wo   = (const float*)d_in[11];
    float* out = (float*)d_out;

    float *qp, *kp, *vp, *attp;
    cudaGetSymbolAddress((void**)&qp,   g_q);
    cudaGetSymbolAddress((void**)&kp,   g_k);
    cudaGetSymbolAddress((void**)&vp,   g_v);
    cudaGetSymbolAddress((void**)&attp, g_att);

    scan_kernel<<<B_, T_>>>(seg, curp);

    sgemm_kernel<<<dim3(QN_/128, M_/128), 256>>>(x, wq, bq, qp, QN_);
    sgemm_kernel<<<dim3(KN_/128, M_/128), 256>>>(x, wk, bk, kp, KN_);
    sgemm_kernel<<<dim3(KN_/128, M_/128), 256>>>(x, wv, bv, vp, KN_);

    rope_kernel<<<(M_*NH_*64 + 255)/256, 256>>>(qp, NH_, M_*NH_*64);
    rope_kernel<<<(M_*KVH_*64 + 255)/256, 256>>>(kp, KVH_, M_*KVH_*64);

    const int att_smem = (2 * 64 * QS_STRIDE + 64 * PS_STRIDE) * (int)sizeof(float);
    cudaFuncSetAttribute(attn_kernel, cudaFuncAttributeMaxDynamicSharedMemorySize, att_smem);
    attn_kernel<<<dim3(T_/64, NH_, B_), 256, att_smem>>>(curp, attp);

    sgemm_kernel<<<dim3(QN_/128, M_/128), 256>>>(attp, wo, nullptr, out, QN_);
}

// round 3
// speedup vs baseline: 1.0026x; 1.0026x over previous
#include <cuda_runtime.h>
#include <cuda_bf16.h>
#include <math.h>

// Problem constants
#define B_    2
#define T_    1024
#define EMB_  3584
#define NH_   28
#define KVH_  4
#define HD_   128
#define NREP_ 7
#define M_    (B_*T_)        // 2048 rows
#define QN_   (NH_*HD_)      // 3584
#define KN_   (KVH_*HD_)     // 512

// Scratch (device globals — no allocation allowed)
__device__ float g_q[(size_t)M_*QN_];
__device__ float g_k[(size_t)M_*KN_];
__device__ float g_v[(size_t)M_*KN_];
__device__ float g_att[(size_t)M_*QN_];
__device__ int   g_pos[B_*T_];
__device__ int   g_start[B_];

// ---------------------------------------------------------------------------
// Segment scan: positions = cumsum(valid)-1+cur_ind ; start = # leading pads
// ---------------------------------------------------------------------------
__global__ void scan_kernel(const int* __restrict__ seg, const int* __restrict__ curp) {
    __shared__ int s[T_];
    __shared__ int cnt;
    int b = blockIdx.x, t = threadIdx.x;
    if (t == 0) cnt = 0;
    int v = (seg[b*T_ + t] != 0) ? 1 : 0;
    s[t] = v;
    __syncthreads();
    for (int off = 1; off < T_; off <<= 1) {
        int x = (t >= off) ? s[t-off] : 0;
        __syncthreads();
        s[t] += x;
        __syncthreads();
    }
    int cum = s[t];
    g_pos[b*T_ + t] = cum - 1 + curp[0];
    if (cum == 0) atomicAdd(&cnt, 1);
    __syncthreads();
    if (t == 0) g_start[b] = cnt;
}

// ---------------------------------------------------------------------------
// RoPE (in place on [b,t,H,HD] tensor). Accurate-enough float path with
// Cody-Waite reduction so it stays correct under --use_fast_math.
// ---------------------------------------------------------------------------
__global__ void rope_kernel(float* __restrict__ x, int H, int total) {
    int idx = blockIdx.x * blockDim.x + threadIdx.x;
    if (idx >= total) return;
    int i  = idx & 63;
    int h  = (idx >> 6) % H;
    int bt = idx / (64 * H);
    int pos = g_pos[bt];
    // timescale = THETA^(2i/HD) = 2^(i * log2(1e6)/64)
    float ts  = exp2f((float)i * 0.311430758895742f);
    float ang = (float)pos / ts;
    // reduce ang mod 2*pi to [-pi, pi]
    float kq = rintf(ang * 0.15915494309189535f);
    float r  = fmaf(-kq, 6.28125f, ang);
    r        = fmaf(-kq, 1.9353071795864769e-3f, r);
    float sv, cv;
    sincosf(r, &sv, &cv);
    float* p = x + ((size_t)bt * H + h) * HD_;
    float x1 = p[i], x2 = p[i + 64];
    p[i]      = x1 * cv - x2 * sv;
    p[i + 64] = x2 * cv + x1 * sv;
}

// ---------------------------------------------------------------------------
// SGEMM: C[M_, N] = A[M_, EMB_] * Bw[EMB_, N] (+bias). 128x128x16 tiles,
// 256 threads, 8x8 per thread, fp32.
// ---------------------------------------------------------------------------
__global__ void __launch_bounds__(256)
sgemm_kernel(const float* __restrict__ A, const float* __restrict__ Bw,
             const float* __restrict__ bias, float* __restrict__ C, int N) {
    __shared__ float As[16][128];
    __shared__ float Bs[16][128];
    const int tid = threadIdx.x;
    const int tx = tid & 15, ty = tid >> 4;
    const int m0 = blockIdx.y * 128, n0 = blockIdx.x * 128;

    float acc[8][8];
    #pragma unroll
    for (int i = 0; i < 8; i++)
        #pragma unroll
        for (int j = 0; j < 8; j++) acc[i][j] = 0.f;

    for (int k0 = 0; k0 < EMB_; k0 += 16) {
        #pragma unroll
        for (int i = 0; i < 2; i++) {
            int lin = tid + 256 * i;         // 0..511 float4s
            int row = lin >> 2, kc = lin & 3;
            float4 v = *(const float4*)&A[(size_t)(m0 + row) * EMB_ + k0 + kc * 4];
            As[kc*4+0][row] = v.x; As[kc*4+1][row] = v.y;
            As[kc*4+2][row] = v.z; As[kc*4+3][row] = v.w;
        }
        #pragma unroll
        for (int i = 0; i < 2; i++) {
            int lin = tid + 256 * i;
            int kr = lin >> 5, nc = lin & 31;
            *(float4*)&Bs[kr][nc*4] =
                *(const float4*)&Bw[(size_t)(k0 + kr) * N + n0 + nc * 4];
        }
        __syncthreads();
        #pragma unroll
        for (int kk = 0; kk < 16; kk++) {
            float a[8], bb[8];
            *(float4*)&a[0]  = *(float4*)&As[kk][ty*4];
            *(float4*)&a[4]  = *(float4*)&As[kk][64 + ty*4];
            *(float4*)&bb[0] = *(float4*)&Bs[kk][tx*4];
            *(float4*)&bb[4] = *(float4*)&Bs[kk][64 + tx*4];
            #pragma unroll
            for (int i = 0; i < 8; i++)
                #pragma unroll
                for (int j = 0; j < 8; j++)
                    acc[i][j] = fmaf(a[i], bb[j], acc[i][j]);
        }
        __syncthreads();
    }

    #pragma unroll
    for (int i = 0; i < 8; i++) {
        int r = (i < 4) ? (ty*4 + i) : (64 + ty*4 + (i - 4));
        #pragma unroll
        for (int jb = 0; jb < 2; jb++) {
            int c = jb ? (64 + tx*4) : (tx*4);
            float4 v;
            v.x = acc[i][jb*4+0]; v.y = acc[i][jb*4+1];
            v.z = acc[i][jb*4+2]; v.w = acc[i][jb*4+3];
            if (bias) {
                v.x += bias[n0 + c + 0]; v.y += bias[n0 + c + 1];
                v.z += bias[n0 + c + 2]; v.w += bias[n0 + c + 3];
            }
            *(float4*)&C[(size_t)(m0 + r) * N + n0 + c] = v;
        }
    }
}

// ---------------------------------------------------------------------------
// Flash attention: 64 q-rows x 64 k-cols tiles, online softmax, fp32.
// grid (T/64, NH, B), 256 threads. K and V share one smem buffer.
// ---------------------------------------------------------------------------
#define QS_STRIDE 132
#define PS_STRIDE 68

__global__ void __launch_bounds__(256)
attn_kernel(const int* __restrict__ curp, float* __restrict__ out) {
    extern __shared__ float sm[];
    float* Qs  = sm;                       // 64 x 132
    float* KVs = sm + 64 * QS_STRIDE;      // 64 x 132
    float* Ps  = sm + 2 * 64 * QS_STRIDE;  // 64 x 68

    const int qt = blockIdx.x, h = blockIdx.y, b = blockIdx.z;
    const int kvh = h / NREP_;
    const int tid = threadIdx.x;
    const int tx = tid & 15, ty = tid >> 4;
    const int cur = curp[0];
    const int start = g_start[b];
    const float scale = 0.08838834764831845f;

    // load Q tile
    #pragma unroll
    for (int i = 0; i < 8; i++) {
        int lin = tid + 256 * i;           // 0..2047 float4s
        int row = lin >> 5, dc = lin & 31;
        float4 v = *(const float4*)&g_q[(((size_t)(b*T_ + qt*64 + row)) * NH_ + h) * HD_ + dc*4];
        *(float4*)&Qs[row * QS_STRIDE + dc*4] = v;
    }

    float o[4][8];
    float m[4], l[4];
    #pragma unroll
    for (int i = 0; i < 4; i++) {
        m[i] = -INFINITY; l[i] = 0.f;
        #pragma unroll
        for (int j = 0; j < 8; j++) o[i][j] = 0.f;
    }

    for (int kt = 0; kt <= qt; kt++) {
        __syncthreads();
        // load K tile
        #pragma unroll
        for (int i = 0; i < 8; i++) {
            int lin = tid + 256 * i;
            int row = lin >> 5, dc = lin & 31;
            float4 v = *(const float4*)&g_k[(((size_t)(b*T_ + kt*64 + row)) * KVH_ + kvh) * HD_ + dc*4];
            *(float4*)&KVs[row * QS_STRIDE + dc*4] = v;
        }
        __syncthreads();

        // S = Q K^T  (rows ty+16i, cols tx+16j)
        float sv[4][4];
        #pragma unroll
        for (int i = 0; i < 4; i++)
            #pragma unroll
            for (int j = 0; j < 4; j++) sv[i][j] = 0.f;
        #pragma unroll 8
        for (int d4 = 0; d4 < 32; d4++) {
            float4 qv[4], kv[4];
            #pragma unroll
            for (int i = 0; i < 4; i++)
                qv[i] = *(float4*)&Qs[(ty + 16*i) * QS_STRIDE + d4*4];
            #pragma unroll
            for (int j = 0; j < 4; j++)
                kv[j] = *(float4*)&KVs[(tx + 16*j) * QS_STRIDE + d4*4];
            #pragma unroll
            for (int i = 0; i < 4; i++)
                #pragma unroll
                for (int j = 0; j < 4; j++) {
                    sv[i][j] = fmaf(qv[i].x, kv[j].x, sv[i][j]);
                    sv[i][j] = fmaf(qv[i].y, kv[j].y, sv[i][j]);
                    sv[i][j] = fmaf(qv[i].z, kv[j].z, sv[i][j]);
                    sv[i][j] = fmaf(qv[i].w, kv[j].w, sv[i][j]);
                }
        }

        // mask + online softmax update
        #pragma unroll
        for (int i = 0; i < 4; i++) {
            int trow = qt*64 + ty + 16*i;
            int qpos = cur + trow - start;
            float mx = -INFINITY;
            #pragma unroll
            for (int j = 0; j < 4; j++) {
                int s = kt*64 + tx + 16*j;
                bool valid = (s >= start) && (s < cur + T_) && ((s - start) <= qpos);
                float val = valid ? sv[i][j] * scale : -INFINITY;
                sv[i][j] = val;
                mx = fmaxf(mx, val);
            }
            #pragma unroll
            for (int w = 8; w >= 1; w >>= 1)
                mx = fmaxf(mx, __shfl_xor_sync(0xffffffffu, mx, w));
            float mnew = fmaxf(m[i], mx);
            float alpha = expf(m[i] - mnew);
            float rs = 0.f;
            #pragma unroll
            for (int j = 0; j < 4; j++) {
                sv[i][j] = expf(sv[i][j] - mnew);
                rs += sv[i][j];
            }
            #pragma unroll
            for (int w = 8; w >= 1; w >>= 1)
                rs += __shfl_xor_sync(0xffffffffu, rs, w);
            l[i] = l[i] * alpha + rs;
            m[i] = mnew;
            #pragma unroll
            for (int j = 0; j < 8; j++) o[i][j] *= alpha;
            // write P
            #pragma unroll
            for (int j = 0; j < 4; j++)
                Ps[(ty + 16*i) * PS_STRIDE + tx + 16*j] = sv[i][j];
        }
        __syncthreads();   // all K reads + P writes done

        // load V tile into the same buffer
        #pragma unroll
        for (int i = 0; i < 8; i++) {
            int lin = tid + 256 * i;
            int row = lin >> 5, dc = lin & 31;
            float4 v = *(const float4*)&g_v[(((size_t)(b*T_ + kt*64 + row)) * KVH_ + kvh) * HD_ + dc*4];
            *(float4*)&KVs[row * QS_STRIDE + dc*4] = v;
        }
        __syncthreads();

        // O += P V   (cols tx*4+{0..3}, 64+tx*4+{0..3})
        #pragma unroll 8
        for (int k = 0; k < 64; k++) {
            float pk[4];
            #pragma unroll
            for (int i = 0; i < 4; i++) pk[i] = Ps[(ty + 16*i) * PS_STRIDE + k];
            float4 v0 = *(float4*)&KVs[k * QS_STRIDE + tx*4];
            float4 v1 = *(float4*)&KVs[k * QS_STRIDE + 64 + tx*4];
            #pragma unroll
            for (int i = 0; i < 4; i++) {
                o[i][0] = fmaf(pk[i], v0.x, o[i][0]);
                o[i][1] = fmaf(pk[i], v0.y, o[i][1]);
                o[i][2] = fmaf(pk[i], v0.z, o[i][2]);
                o[i][3] = fmaf(pk[i], v0.w, o[i][3]);
                o[i][4] = fmaf(pk[i], v1.x, o[i][4]);
                o[i][5] = fmaf(pk[i], v1.y, o[i][5]);
                o[i][6] = fmaf(pk[i], v1.z, o[i][6]);
                o[i][7] = fmaf(pk[i], v1.w, o[i][7]);
            }
        }
    }

    // normalize + store
    #pragma unroll
    for (int i = 0; i < 4; i++) {
        float inv = 1.0f / l[i];
        int trow = qt*64 + ty + 16*i;
        size_t base = (((size_t)(b*T_ + trow)) * NH_ + h) * HD_;
        float4 r0, r1;
        r0.x = o[i][0]*inv; r0.y = o[i][1]*inv; r0.z = o[i][2]*inv; r0.w = o[i][3]*inv;
        r1.x = o[i][4]*inv; r1.y = o[i][5]*inv; r1.z = o[i][6]*inv; r1.w = o[i][7]*inv;
        *(float4*)&out[base + tx*4]      = r0;
        *(float4*)&out[base + 64 + tx*4] = r1;
    }
}

// ---------------------------------------------------------------------------
// Launch
// ---------------------------------------------------------------------------
extern "C" void kernel_launch(void* const* d_in, const int* in_sizes, int n_in,
                              void* d_out, int out_size) {
    const float* x    = (const float*)d_in[0];
    const int*   seg  = (const int*)  d_in[1];
    // d_in[2], d_in[3]: k_cache/v_cache — unused (cur_ind=0, all keys fresh)
    const int*   curp = (const int*)  d_in[4];
    const float* wq   = (const float*)d_in[5];
    const float* bq   = (const float*)d_in[6];
    const float* wk   = (const float*)d_in[7];
    const float* bk   = (const float*)d_in[8];
    const float* wv   = (const float*)d_in[9];
    const float* bv   = (const float*)d_in[10];
    const float* wo   = (const float*)d_in[11];
    float* out = (float*)d_out;

    float *qp, *kp, *vp, *attp;
    cudaGetSymbolAddress((void**)&qp,   g_q);
    cudaGetSymbolAddress((void**)&kp,   g_k);
    cudaGetSymbolAddress((void**)&vp,   g_v);
    cudaGetSymbolAddress((void**)&attp, g_att);

    scan_kernel<<<B_, T_>>>(seg, curp);

    sgemm_kernel<<<dim3(QN_/128, M_/128), 256>>>(x, wq, bq, qp, QN_);
    sgemm_kernel<<<dim3(KN_/128, M_/128), 256>>>(x, wk, bk, kp, KN_);
    sgemm_kernel<<<dim3(KN_/128, M_/128), 256>>>(x, wv, bv, vp, KN_);

    rope_kernel<<<(M_*NH_*64 + 255)/256, 256>>>(qp, NH_, M_*NH_*64);
    rope_kernel<<<(M_*KVH_*64 + 255)/256, 256>>>(kp, KVH_, M_*KVH_*64);

    const int att_smem = (2 * 64 * QS_STRIDE + 64 * PS_STRIDE) * (int)sizeof(float);
    cudaFuncSetAttribute(attn_kernel, cudaFuncAttributeMaxDynamicSharedMemorySize, att_smem);
    attn_kernel<<<dim3(T_/64, NH_, B_), 256, att_smem>>>(curp, attp);

    sgemm_kernel<<<dim3(QN_/128, M_/128), 256>>>(attp, wo, nullptr, out, QN_);
}